// round 15
// baseline (speedup 1.0000x reference)
#include <cuda_runtime.h>
#include <math.h>
#include <float.h>

// Problem constants
#define B_DIM 32
#define C_DIM 9
#define T_DIM 4096
#define NROWS (B_DIM * T_DIM)          // 131072
#define NHALF (NROWS / 2)              // 65536
#define NCODES 512
#define CODE_DIM 64
#define HALF_DIM 32
#define PDIM 12                        // 11 feature dims + bias
#define DROW (PDIM * 2)                // 24 floats per code (lane-duplicated)
#define SCORE_SHIFT 32.0f
#define FIX_THR 3e-4f                  // raw fp32 gap threshold

#define IDX_OFF (NROWS * CODE_DIM)     // 8388608
#define PH_OFF (IDX_OFF + NROWS)       // 8519680

// Scratch (no cudaMalloc allowed)
__device__ float  g_phase_scratch[B_DIM * C_DIM * T_DIM];
__device__ float  g_p32d[NCODES * DROW];     // lane-duplicated fp32 (shifted bias)
__device__ double g_p64[NCODES * PDIM];      // exact (unshifted)

// ---------------------------------------------------------------------------
// FFT helpers (radix-4, 4096 = 4^6)
// ---------------------------------------------------------------------------
__device__ __forceinline__ float2 cmul(float2 a, float2 b) {
    return make_float2(fmaf(a.x, b.x, -a.y * b.y), fmaf(a.x, b.y, a.y * b.x));
}

// DIT stages [sstart..5]: digit-reversed input -> natural output.
__device__ void fft4096_r4_dit(float2* __restrict__ buf,
                               const float2* __restrict__ tw, int tid, int sstart) {
    #pragma unroll 1
    for (int s = sstart; s < 6; s++) {
        int quarter = 1 << (2 * s);
        int rstep   = 1024 >> (2 * s);
        #pragma unroll
        for (int q = tid; q < 1024; q += 512) {
            int j   = q & (quarter - 1);
            int grp = q >> (2 * s);
            int pos = grp * (quarter << 2) + j;

            float2 w1 = tw[j * rstep];
            float2 w2 = cmul(w1, w1);
            float2 w3 = cmul(w2, w1);

            float2 a0 = buf[pos];
            float2 a1 = cmul(buf[pos + quarter],     w1);
            float2 a2 = cmul(buf[pos + 2 * quarter], w2);
            float2 a3 = cmul(buf[pos + 3 * quarter], w3);

            float2 t0 = make_float2(a0.x + a2.x, a0.y + a2.y);
            float2 t1 = make_float2(a0.x - a2.x, a0.y - a2.y);
            float2 t2 = make_float2(a1.x + a3.x, a1.y + a3.y);
            float2 t3 = make_float2(a1.x - a3.x, a1.y - a3.y);

            buf[pos]               = make_float2(t0.x + t2.x, t0.y + t2.y);
            buf[pos + quarter]     = make_float2(t1.x + t3.y, t1.y - t3.x);
            buf[pos + 2 * quarter] = make_float2(t0.x - t2.x, t0.y - t2.y);
            buf[pos + 3 * quarter] = make_float2(t1.x - t3.y, t1.y + t3.x);
        }
        __syncthreads();
    }
}

// DIF: natural input -> digit-reversed output.
__device__ void fft4096_r4_dif(float2* __restrict__ buf,
                               const float2* __restrict__ tw, int tid) {
    #pragma unroll 1
    for (int s = 0; s < 6; s++) {
        int quarter = 1024 >> (2 * s);
        int tstep   = 1 << (2 * s);
        int shift   = 10 - 2 * s;
        #pragma unroll
        for (int q = tid; q < 1024; q += 512) {
            int j   = q & (quarter - 1);
            int grp = q >> shift;
            int pos = grp * (quarter << 2) + j;

            float2 a0 = buf[pos];
            float2 a1 = buf[pos + quarter];
            float2 a2 = buf[pos + 2 * quarter];
            float2 a3 = buf[pos + 3 * quarter];

            float2 t0 = make_float2(a0.x + a2.x, a0.y + a2.y);
            float2 t1 = make_float2(a0.x - a2.x, a0.y - a2.y);
            float2 t2 = make_float2(a1.x + a3.x, a1.y + a3.y);
            float2 t3 = make_float2(a1.x - a3.x, a1.y - a3.y);

            float2 b0 = make_float2(t0.x + t2.x, t0.y + t2.y);
            float2 b1 = make_float2(t1.x + t3.y, t1.y - t3.x);
            float2 b2 = make_float2(t0.x - t2.x, t0.y - t2.y);
            float2 b3 = make_float2(t1.x - t3.y, t1.y + t3.x);

            float2 w1 = tw[j * tstep];
            float2 w2 = cmul(w1, w1);
            float2 w3 = cmul(w2, w1);

            buf[pos]               = b0;
            buf[pos + quarter]     = cmul(b1, w1);
            buf[pos + 2 * quarter] = cmul(b2, w2);
            buf[pos + 3 * quarter] = cmul(b3, w3);
        }
        __syncthreads();
    }
}

// ---------------------------------------------------------------------------
// Kernel 1: analytic-signal phase. DIF fwd; Hilbert*conj fused into DIT
// stage 0; DIT stages 1..5; atan2.
// ---------------------------------------------------------------------------
__global__ void phase_kernel(const float* __restrict__ imu) {
    extern __shared__ float2 sm[];
    float2* buf = sm;          // 4096
    float2* tw  = sm + 4096;   // 1024

    int tid = threadIdx.x;
    int bc  = blockIdx.x;      // 0..287

    for (int k = tid; k < 1024; k += 512) {
        float sv, cv;
        sincospif(-(float)k * (1.0f / 2048.0f), &sv, &cv);
        tw[k] = make_float2(cv, sv);
    }

    const float* x = imu + (size_t)bc * T_DIM;
    for (int i = tid; i < 4096; i += 512) {
        buf[i] = make_float2(x[i], 0.0f);
    }
    __syncthreads();

    fft4096_r4_dif(buf, tw, tid);

    // Fused Hilbert + conj + DIT stage 0
    for (int g = tid; g < 1024; g += 512) {
        int pos = g * 4;
        float2 x0 = buf[pos];
        float2 x1 = buf[pos + 1];
        float2 a1 = make_float2(2.0f * x1.x, -2.0f * x1.y);
        float2 t0, t1;
        if (g == 0) {
            float2 x2 = buf[2];
            float2 a0 = make_float2(x0.x, -x0.y);
            float2 a2 = make_float2(x2.x, -x2.y);
            t0 = make_float2(a0.x + a2.x, a0.y + a2.y);
            t1 = make_float2(a0.x - a2.x, a0.y - a2.y);
        } else {
            float2 a0 = make_float2(2.0f * x0.x, -2.0f * x0.y);
            t0 = a0;
            t1 = a0;
        }
        buf[pos]     = make_float2(t0.x + a1.x, t0.y + a1.y);
        buf[pos + 1] = make_float2(t1.x + a1.y, t1.y - a1.x);
        buf[pos + 2] = make_float2(t0.x - a1.x, t0.y - a1.y);
        buf[pos + 3] = make_float2(t1.x - a1.y, t1.y + a1.x);
    }
    __syncthreads();

    fft4096_r4_dit(buf, tw, tid, 1);

    float* dst = g_phase_scratch + (size_t)bc * T_DIM;
    for (int i = tid; i < 4096; i += 512) {
        float2 z = buf[i];
        dst[i] = atan2f(-z.y, z.x);
    }
}

// ---------------------------------------------------------------------------
// Kernel 2: precompute per-code projected 12-dim tables
// ---------------------------------------------------------------------------
__device__ __forceinline__ double warp_sum_d(double v) {
    #pragma unroll
    for (int m = 16; m > 0; m >>= 1) v += __shfl_xor_sync(0xFFFFFFFFu, v, m);
    return v;
}

__global__ void precompute_kernel(const float* __restrict__ W_mag,
                                  const float* __restrict__ b_mag,
                                  const float* __restrict__ W_phase,
                                  const float* __restrict__ b_phase,
                                  const float* __restrict__ codebook) {
    int k = blockIdx.x;
    int d = threadIdx.x;     // 0..31
    const float* c = codebook + k * CODE_DIM;

    double cm = (double)c[d];
    double cp = (double)c[HALF_DIM + d];

    double u[9], v[9];
    #pragma unroll
    for (int i = 0; i < 9; i++) {
        u[i] = (double)W_mag[d * 9 + i] * cm;
        v[i] = (double)W_phase[d * 9 + i] * cp;
    }
    double w = (double)b_mag[d] * cm + (double)b_phase[d] * cp
             - 0.5 * (cm * cm + cp * cp);

    double p[PDIM];
    #pragma unroll
    for (int i = 0; i < 7; i++) p[i] = warp_sum_d(u[i] + v[i]);
    p[7]  = warp_sum_d(u[7]);
    p[8]  = warp_sum_d(u[8]);
    p[9]  = warp_sum_d(v[7]);
    p[10] = warp_sum_d(v[8]);
    p[11] = warp_sum_d(w);

    if (d == 0) {
        #pragma unroll
        for (int i = 0; i < PDIM; i++) {
            g_p64[k * PDIM + i] = p[i];
            float f = (float)p[i];
            if (i == 11) f = (float)(p[i] + (double)SCORE_SHIFT);
            g_p32d[k * DROW + i * 2]     = f;
            g_p32d[k * DROW + i * 2 + 1] = f;
        }
    }
}

// ---------------------------------------------------------------------------
// Kernel 3: argmax; 2 rows per thread (f32x2 lanes), broadcast smem reads,
// raw-score setp/sel tracking. Near-ties handled INLINE: scalar fp32 rescan
// of the smem table collecting candidates, then exact fp64 rerank.
// ---------------------------------------------------------------------------
__device__ __forceinline__ unsigned long long pack2(float lo, float hi) {
    unsigned long long r;
    asm("mov.b64 %0, {%1, %2};" : "=l"(r) : "f"(lo), "f"(hi));
    return r;
}
__device__ __forceinline__ void unpack2(unsigned long long v, float& lo, float& hi) {
    asm("mov.b64 {%0, %1}, %2;" : "=f"(lo), "=f"(hi) : "l"(v));
}
__device__ __forceinline__ unsigned long long fma2(unsigned long long a,
                                                   unsigned long long b,
                                                   unsigned long long c) {
    unsigned long long d;
    asm("fma.rn.f32x2 %0, %1, %2, %3;" : "=l"(d) : "l"(a), "l"(b), "l"(c));
    return d;
}

__device__ __forceinline__ void load_features(const float* __restrict__ imu,
                                              int row, float* g, float& ph) {
    int b = row >> 12;
    int t = row & 4095;
    const float* phbase = g_phase_scratch + (size_t)(b * C_DIM) * T_DIM + t;
    float s = 0.0f;
    #pragma unroll
    for (int c = 0; c < 9; c++) s += phbase[(size_t)c * T_DIM];
    ph = s * (1.0f / 9.0f);
    const float* ib = imu + (size_t)(b * C_DIM) * T_DIM + t;
    #pragma unroll
    for (int c = 0; c < 9; c++) g[c] = ib[(size_t)c * T_DIM];
    g[9]  = cosf(ph);
    g[10] = sinf(ph);
}

// Rare path: exact argmax via candidate collection (fp32) + fp64 rerank.
__device__ __noinline__ int exact_rerank(const float* __restrict__ sp,
                                         const float* __restrict__ g,
                                         float bestApprox, int bidx0) {
    float thr = bestApprox - 1e-3f;     // wide margin over fp32 rounding
    int cand[16];
    int nc = 0;
    #pragma unroll 1
    for (int j = 0; j < NCODES; j++) {
        const float* pr = sp + j * DROW;
        float s = pr[22];               // bias (dup slot 11)
        #pragma unroll
        for (int k = 0; k < 11; k++) s = fmaf(g[k], pr[k * 2], s);
        if (s >= thr && nc < 16) cand[nc++] = j;
    }
    double gd[11];
    #pragma unroll
    for (int k = 0; k < 11; k++) gd[k] = (double)g[k];
    double bd = -1.0e300;
    int bi = bidx0;
    #pragma unroll 1
    for (int m = 0; m < nc; m++) {
        int j = cand[m];
        const double* pr = g_p64 + j * PDIM;
        double s0 = pr[11];
        double s1 = 0.0;
        #pragma unroll
        for (int k = 0; k < 10; k += 2) {
            s0 += gd[k]     * pr[k];
            s1 += gd[k + 1] * pr[k + 1];
        }
        s0 += gd[10] * pr[10];
        double s = s0 + s1;
        if (s > bd) { bd = s; bi = j; }   // cand ascending -> lowest idx wins
    }
    return bi;
}

__global__ void __launch_bounds__(256) quantize_kernel(
    const float* __restrict__ imu,
    const float* __restrict__ codebook,
    float* __restrict__ out) {

    __shared__ __align__(16) float sp[NCODES * DROW];   // 48 KB
    int tid = threadIdx.x;
    {
        const float4* src = (const float4*)g_p32d;
        float4* dst = (float4*)sp;
        for (int i = tid; i < NCODES * DROW / 4; i += 256) dst[i] = src[i];
    }
    __syncthreads();

    int gid = blockIdx.x * 256 + tid;
    int r0 = gid;
    int r1 = gid + NHALF;

    float g0[11], g1[11], ph0, ph1;
    load_features(imu, r0, g0, ph0);
    load_features(imu, r1, g1, ph1);

    unsigned long long gp[11];
    #pragma unroll
    for (int i = 0; i < 11; i++) gp[i] = pack2(g0[i], g1[i]);

    float best0 = -FLT_MAX, b20 = -FLT_MAX;
    float best1 = -FLT_MAX, b21 = -FLT_MAX;
    int bidx0 = 0, bidx1 = 0;

    #pragma unroll 4
    for (int jj = 0; jj < NCODES; jj++) {
        const ulonglong2* pr = (const ulonglong2*)(sp + jj * DROW);  // broadcast
        ulonglong2 v0 = pr[0], v1 = pr[1], v2 = pr[2];
        ulonglong2 v3 = pr[3], v4 = pr[4], v5 = pr[5];
        unsigned long long acc = v5.y;
        acc = fma2(gp[0],  v0.x, acc);
        acc = fma2(gp[1],  v0.y, acc);
        acc = fma2(gp[2],  v1.x, acc);
        acc = fma2(gp[3],  v1.y, acc);
        acc = fma2(gp[4],  v2.x, acc);
        acc = fma2(gp[5],  v2.y, acc);
        acc = fma2(gp[6],  v3.x, acc);
        acc = fma2(gp[7],  v3.y, acc);
        acc = fma2(gp[8],  v4.x, acc);
        acc = fma2(gp[9],  v4.y, acc);
        acc = fma2(gp[10], v5.x, acc);
        float s0, s1;
        unpack2(acc, s0, s1);
        b20 = fmaxf(b20, fminf(s0, best0));
        bool c0 = s0 > best0;                 // strict > keeps lowest index
        best0 = fmaxf(best0, s0);
        bidx0 = c0 ? jj : bidx0;
        b21 = fmaxf(b21, fminf(s1, best1));
        bool c1 = s1 > best1;
        best1 = fmaxf(best1, s1);
        bidx1 = c1 ? jj : bidx1;
    }

    // Rare near-ties: exact inline rerank (fp32 candidates -> fp64)
    if (best0 - b20 < FIX_THR) bidx0 = exact_rerank(sp, g0, best0, bidx0);
    if (best1 - b21 < FIX_THR) bidx1 = exact_rerank(sp, g1, best1, bidx1);

    out[IDX_OFF + r0] = (float)bidx0;
    out[IDX_OFF + r1] = (float)bidx1;
    out[PH_OFF + r0] = ph0;
    out[PH_OFF + r1] = ph1;

    // Warp-cooperative coalesced gather: warp's rows are contiguous.
    int lane = tid & 31;
    int wrow0 = gid & ~31;
    const float4* cb4 = (const float4*)codebook;
    float4* o4 = (float4*)out;
    #pragma unroll
    for (int i = 0; i < 16; i++) {
        int f = i * 32 + lane;          // 0..511 float4s in warp region
        int rsel = f >> 4;              // row-within-warp 0..31
        int col  = f & 15;
        int bs0 = __shfl_sync(0xFFFFFFFFu, bidx0, rsel);
        o4[(size_t)(wrow0 + rsel) * 16 + col] = cb4[bs0 * 16 + col];
    }
    int wrow1 = wrow0 + NHALF;
    #pragma unroll
    for (int i = 0; i < 16; i++) {
        int f = i * 32 + lane;
        int rsel = f >> 4;
        int col  = f & 15;
        int bs1 = __shfl_sync(0xFFFFFFFFu, bidx1, rsel);
        o4[(size_t)(wrow1 + rsel) * 16 + col] = cb4[bs1 * 16 + col];
    }
}

// ---------------------------------------------------------------------------
extern "C" void kernel_launch(void* const* d_in, const int* in_sizes, int n_in,
                              void* d_out, int out_size) {
    const float* imu      = (const float*)d_in[0];
    const float* W_mag    = (const float*)d_in[1];
    const float* b_mag    = (const float*)d_in[2];
    const float* W_phase  = (const float*)d_in[3];
    const float* b_phase  = (const float*)d_in[4];
    const float* codebook = (const float*)d_in[5];
    float* out = (float*)d_out;

    phase_kernel<<<B_DIM * C_DIM, 512, 5120 * sizeof(float2)>>>(imu);
    precompute_kernel<<<NCODES, 32>>>(W_mag, b_mag, W_phase, b_phase, codebook);
    quantize_kernel<<<NHALF / 256, 256>>>(imu, codebook, out);
}

// round 16
// speedup vs baseline: 1.2253x; 1.2253x over previous
#include <cuda_runtime.h>
#include <math.h>
#include <float.h>

// Problem constants
#define B_DIM 32
#define C_DIM 9
#define T_DIM 4096
#define NROWS (B_DIM * T_DIM)          // 131072
#define NHALF (NROWS / 2)              // 65536
#define NCODES 512
#define CODE_DIM 64
#define HALF_DIM 32
#define PDIM 12                        // 11 feature dims + bias
#define PSTRIDE 13                     // padded stride for fixup smem table
#define DROW (PDIM * 2)                // 24 floats per code (lane-duplicated)
#define SCORE_SHIFT 32.0f

#define IDX_OFF (NROWS * CODE_DIM)     // 8388608
#define PH_OFF (IDX_OFF + NROWS)       // 8519680

// Scratch (no cudaMalloc allowed)
__device__ float  g_phase_scratch[B_DIM * C_DIM * T_DIM];
__device__ float  g_p32d[NCODES * DROW];     // lane-duplicated fp32 (shifted bias)
__device__ float  g_p32s[NCODES * PSTRIDE];  // compact padded fp32 (shifted bias)
__device__ double g_p64[NCODES * PDIM];      // exact (unshifted)
__device__ int    g_fix_count;
__device__ int    g_fix_list[NROWS];

// ---------------------------------------------------------------------------
// FFT helpers (radix-4, 4096 = 4^6)
// ---------------------------------------------------------------------------
__device__ __forceinline__ float2 cmul(float2 a, float2 b) {
    return make_float2(fmaf(a.x, b.x, -a.y * b.y), fmaf(a.x, b.y, a.y * b.x));
}

// DIT stages [sstart..5]: digit-reversed input -> natural output.
__device__ void fft4096_r4_dit(float2* __restrict__ buf,
                               const float2* __restrict__ tw, int tid, int sstart) {
    #pragma unroll 1
    for (int s = sstart; s < 6; s++) {
        int quarter = 1 << (2 * s);
        int rstep   = 1024 >> (2 * s);
        #pragma unroll
        for (int q = tid; q < 1024; q += 512) {
            int j   = q & (quarter - 1);
            int grp = q >> (2 * s);
            int pos = grp * (quarter << 2) + j;

            float2 w1 = tw[j * rstep];
            float2 w2 = cmul(w1, w1);
            float2 w3 = cmul(w2, w1);

            float2 a0 = buf[pos];
            float2 a1 = cmul(buf[pos + quarter],     w1);
            float2 a2 = cmul(buf[pos + 2 * quarter], w2);
            float2 a3 = cmul(buf[pos + 3 * quarter], w3);

            float2 t0 = make_float2(a0.x + a2.x, a0.y + a2.y);
            float2 t1 = make_float2(a0.x - a2.x, a0.y - a2.y);
            float2 t2 = make_float2(a1.x + a3.x, a1.y + a3.y);
            float2 t3 = make_float2(a1.x - a3.x, a1.y - a3.y);

            buf[pos]               = make_float2(t0.x + t2.x, t0.y + t2.y);
            buf[pos + quarter]     = make_float2(t1.x + t3.y, t1.y - t3.x);
            buf[pos + 2 * quarter] = make_float2(t0.x - t2.x, t0.y - t2.y);
            buf[pos + 3 * quarter] = make_float2(t1.x - t3.y, t1.y + t3.x);
        }
        __syncthreads();
    }
}

// DIF: natural input -> digit-reversed output.
__device__ void fft4096_r4_dif(float2* __restrict__ buf,
                               const float2* __restrict__ tw, int tid) {
    #pragma unroll 1
    for (int s = 0; s < 6; s++) {
        int quarter = 1024 >> (2 * s);
        int tstep   = 1 << (2 * s);
        int shift   = 10 - 2 * s;
        #pragma unroll
        for (int q = tid; q < 1024; q += 512) {
            int j   = q & (quarter - 1);
            int grp = q >> shift;
            int pos = grp * (quarter << 2) + j;

            float2 a0 = buf[pos];
            float2 a1 = buf[pos + quarter];
            float2 a2 = buf[pos + 2 * quarter];
            float2 a3 = buf[pos + 3 * quarter];

            float2 t0 = make_float2(a0.x + a2.x, a0.y + a2.y);
            float2 t1 = make_float2(a0.x - a2.x, a0.y - a2.y);
            float2 t2 = make_float2(a1.x + a3.x, a1.y + a3.y);
            float2 t3 = make_float2(a1.x - a3.x, a1.y - a3.y);

            float2 b0 = make_float2(t0.x + t2.x, t0.y + t2.y);
            float2 b1 = make_float2(t1.x + t3.y, t1.y - t3.x);
            float2 b2 = make_float2(t0.x - t2.x, t0.y - t2.y);
            float2 b3 = make_float2(t1.x - t3.y, t1.y + t3.x);

            float2 w1 = tw[j * tstep];
            float2 w2 = cmul(w1, w1);
            float2 w3 = cmul(w2, w1);

            buf[pos]               = b0;
            buf[pos + quarter]     = cmul(b1, w1);
            buf[pos + 2 * quarter] = cmul(b2, w2);
            buf[pos + 3 * quarter] = cmul(b3, w3);
        }
        __syncthreads();
    }
}

// ---------------------------------------------------------------------------
// Kernel 1: analytic-signal phase. DIF fwd; Hilbert*conj fused into DIT
// stage 0; DIT stages 1..5; atan2.
// ---------------------------------------------------------------------------
__global__ void phase_kernel(const float* __restrict__ imu) {
    extern __shared__ float2 sm[];
    float2* buf = sm;          // 4096
    float2* tw  = sm + 4096;   // 1024

    int tid = threadIdx.x;
    int bc  = blockIdx.x;      // 0..287

    for (int k = tid; k < 1024; k += 512) {
        float sv, cv;
        sincospif(-(float)k * (1.0f / 2048.0f), &sv, &cv);
        tw[k] = make_float2(cv, sv);
    }

    const float* x = imu + (size_t)bc * T_DIM;
    for (int i = tid; i < 4096; i += 512) {
        buf[i] = make_float2(x[i], 0.0f);
    }
    __syncthreads();

    fft4096_r4_dif(buf, tw, tid);

    // Fused Hilbert + conj + DIT stage 0
    for (int g = tid; g < 1024; g += 512) {
        int pos = g * 4;
        float2 x0 = buf[pos];
        float2 x1 = buf[pos + 1];
        float2 a1 = make_float2(2.0f * x1.x, -2.0f * x1.y);
        float2 t0, t1;
        if (g == 0) {
            float2 x2 = buf[2];
            float2 a0 = make_float2(x0.x, -x0.y);
            float2 a2 = make_float2(x2.x, -x2.y);
            t0 = make_float2(a0.x + a2.x, a0.y + a2.y);
            t1 = make_float2(a0.x - a2.x, a0.y - a2.y);
        } else {
            float2 a0 = make_float2(2.0f * x0.x, -2.0f * x0.y);
            t0 = a0;
            t1 = a0;
        }
        buf[pos]     = make_float2(t0.x + a1.x, t0.y + a1.y);
        buf[pos + 1] = make_float2(t1.x + a1.y, t1.y - a1.x);
        buf[pos + 2] = make_float2(t0.x - a1.x, t0.y - a1.y);
        buf[pos + 3] = make_float2(t1.x - a1.y, t1.y + a1.x);
    }
    __syncthreads();

    fft4096_r4_dit(buf, tw, tid, 1);

    float* dst = g_phase_scratch + (size_t)bc * T_DIM;
    for (int i = tid; i < 4096; i += 512) {
        float2 z = buf[i];
        dst[i] = atan2f(-z.y, z.x);
    }
}

// ---------------------------------------------------------------------------
// Kernel 2: precompute per-code projected 12-dim tables
// ---------------------------------------------------------------------------
__device__ __forceinline__ double warp_sum_d(double v) {
    #pragma unroll
    for (int m = 16; m > 0; m >>= 1) v += __shfl_xor_sync(0xFFFFFFFFu, v, m);
    return v;
}

__global__ void precompute_kernel(const float* __restrict__ W_mag,
                                  const float* __restrict__ b_mag,
                                  const float* __restrict__ W_phase,
                                  const float* __restrict__ b_phase,
                                  const float* __restrict__ codebook) {
    int k = blockIdx.x;
    int d = threadIdx.x;     // 0..31
    const float* c = codebook + k * CODE_DIM;

    if (k == 0 && d == 0) g_fix_count = 0;

    double cm = (double)c[d];
    double cp = (double)c[HALF_DIM + d];

    double u[9], v[9];
    #pragma unroll
    for (int i = 0; i < 9; i++) {
        u[i] = (double)W_mag[d * 9 + i] * cm;
        v[i] = (double)W_phase[d * 9 + i] * cp;
    }
    double w = (double)b_mag[d] * cm + (double)b_phase[d] * cp
             - 0.5 * (cm * cm + cp * cp);

    double p[PDIM];
    #pragma unroll
    for (int i = 0; i < 7; i++) p[i] = warp_sum_d(u[i] + v[i]);
    p[7]  = warp_sum_d(u[7]);
    p[8]  = warp_sum_d(u[8]);
    p[9]  = warp_sum_d(v[7]);
    p[10] = warp_sum_d(v[8]);
    p[11] = warp_sum_d(w);

    if (d == 0) {
        #pragma unroll
        for (int i = 0; i < PDIM; i++) {
            g_p64[k * PDIM + i] = p[i];
            float f = (float)p[i];
            if (i == 11) f = (float)(p[i] + (double)SCORE_SHIFT);
            g_p32s[k * PSTRIDE + i] = f;
            g_p32d[k * DROW + i * 2]     = f;
            g_p32d[k * DROW + i * 2 + 1] = f;
        }
    }
}

// ---------------------------------------------------------------------------
// Kernel 3: argmax; 2 rows per thread (f32x2 lanes). Broadcast smem reads,
// two 256-code sub-loops with 8-bit index embed, FMNMX tracking.
// Near-ties flagged (dynamic tight threshold) for the fixup kernel.
// ---------------------------------------------------------------------------
__device__ __forceinline__ unsigned long long pack2(float lo, float hi) {
    unsigned long long r;
    asm("mov.b64 %0, {%1, %2};" : "=l"(r) : "f"(lo), "f"(hi));
    return r;
}
__device__ __forceinline__ void unpack2(unsigned long long v, float& lo, float& hi) {
    asm("mov.b64 {%0, %1}, %2;" : "=f"(lo), "=f"(hi) : "l"(v));
}
__device__ __forceinline__ unsigned long long fma2(unsigned long long a,
                                                   unsigned long long b,
                                                   unsigned long long c) {
    unsigned long long d;
    asm("fma.rn.f32x2 %0, %1, %2, %3;" : "=l"(d) : "l"(a), "l"(b), "l"(c));
    return d;
}

__device__ __forceinline__ void load_features(const float* __restrict__ imu,
                                              int row, float* g, float& ph) {
    int b = row >> 12;
    int t = row & 4095;
    const float* phbase = g_phase_scratch + (size_t)(b * C_DIM) * T_DIM + t;
    float s = 0.0f;
    #pragma unroll
    for (int c = 0; c < 9; c++) s += phbase[(size_t)c * T_DIM];
    ph = s * (1.0f / 9.0f);
    const float* ib = imu + (size_t)(b * C_DIM) * T_DIM + t;
    #pragma unroll
    for (int c = 0; c < 9; c++) g[c] = ib[(size_t)c * T_DIM];
    g[9]  = cosf(ph);
    g[10] = sinf(ph);
}

__device__ __forceinline__ float embed8(float s, unsigned ikey) {
    return __uint_as_float((__float_as_uint(s) & 0xFFFFFF00u) | ikey);
}

// Tight upper bound on (embed perturbation + fp32-vs-fp64 dot error) of a gap:
// 2 * 256 ulp(|best|) + accumulation error. ulp(x) = 2^-23 x -> 6.2e-5 |best|.
__device__ __forceinline__ float fix_thr(float best) {
    return fmaf(fabsf(best), 7e-5f, 1e-4f);
}

__global__ void __launch_bounds__(256, 3) quantize_kernel(
    const float* __restrict__ imu,
    const float* __restrict__ codebook,
    float* __restrict__ out) {

    __shared__ __align__(16) float sp[NCODES * DROW];   // 48 KB
    int tid = threadIdx.x;
    {
        const float4* src = (const float4*)g_p32d;
        float4* dst = (float4*)sp;
        for (int i = tid; i < NCODES * DROW / 4; i += 256) dst[i] = src[i];
    }
    __syncthreads();

    int gid = blockIdx.x * 256 + tid;
    int r0 = gid;
    int r1 = gid + NHALF;

    float g0[11], g1[11], ph0, ph1;
    load_features(imu, r0, g0, ph0);
    load_features(imu, r1, g1, ph1);

    unsigned long long gp[11];
    #pragma unroll
    for (int i = 0; i < 11; i++) gp[i] = pack2(g0[i], g1[i]);

    // bests per (half, row)
    float bA0 = -FLT_MAX, b2A0 = -FLT_MAX, bA1 = -FLT_MAX, b2A1 = -FLT_MAX;
    float bB0 = -FLT_MAX, b2B0 = -FLT_MAX, bB1 = -FLT_MAX, b2B1 = -FLT_MAX;

    #pragma unroll 4
    for (int jj = 0; jj < 256; jj++) {
        const ulonglong2* pr = (const ulonglong2*)(sp + jj * DROW);  // broadcast
        ulonglong2 v0 = pr[0], v1 = pr[1], v2 = pr[2];
        ulonglong2 v3 = pr[3], v4 = pr[4], v5 = pr[5];
        unsigned long long acc = v5.y;
        acc = fma2(gp[0],  v0.x, acc);
        acc = fma2(gp[1],  v0.y, acc);
        acc = fma2(gp[2],  v1.x, acc);
        acc = fma2(gp[3],  v1.y, acc);
        acc = fma2(gp[4],  v2.x, acc);
        acc = fma2(gp[5],  v2.y, acc);
        acc = fma2(gp[6],  v3.x, acc);
        acc = fma2(gp[7],  v3.y, acc);
        acc = fma2(gp[8],  v4.x, acc);
        acc = fma2(gp[9],  v4.y, acc);
        acc = fma2(gp[10], v5.x, acc);
        float s0, s1;
        unpack2(acc, s0, s1);
        unsigned ikey = 255u - (unsigned)jj;
        float e0 = embed8(s0, ikey);
        float e1 = embed8(s1, ikey);
        b2A0 = fmaxf(b2A0, fminf(e0, bA0));  bA0 = fmaxf(bA0, e0);
        b2A1 = fmaxf(b2A1, fminf(e1, bA1));  bA1 = fmaxf(bA1, e1);
    }
    #pragma unroll 4
    for (int jj = 0; jj < 256; jj++) {
        const ulonglong2* pr = (const ulonglong2*)(sp + (256 + jj) * DROW);
        ulonglong2 v0 = pr[0], v1 = pr[1], v2 = pr[2];
        ulonglong2 v3 = pr[3], v4 = pr[4], v5 = pr[5];
        unsigned long long acc = v5.y;
        acc = fma2(gp[0],  v0.x, acc);
        acc = fma2(gp[1],  v0.y, acc);
        acc = fma2(gp[2],  v1.x, acc);
        acc = fma2(gp[3],  v1.y, acc);
        acc = fma2(gp[4],  v2.x, acc);
        acc = fma2(gp[5],  v2.y, acc);
        acc = fma2(gp[6],  v3.x, acc);
        acc = fma2(gp[7],  v3.y, acc);
        acc = fma2(gp[8],  v4.x, acc);
        acc = fma2(gp[9],  v4.y, acc);
        acc = fma2(gp[10], v5.x, acc);
        float s0, s1;
        unpack2(acc, s0, s1);
        unsigned ikey = 255u - (unsigned)jj;
        float e0 = embed8(s0, ikey);
        float e1 = embed8(s1, ikey);
        b2B0 = fmaxf(b2B0, fminf(e0, bB0));  bB0 = fmaxf(bB0, e0);
        b2B1 = fmaxf(b2B1, fminf(e1, bB1));  bB1 = fmaxf(bB1, e1);
    }

    // merge halves (A preferred on equal embedded value -> lower index)
    float m0  = fmaxf(bA0, bB0);
    float m20 = fmaxf(fminf(bA0, bB0), fmaxf(b2A0, b2B0));
    int bidx0 = (bA0 >= bB0)
              ? (255 - (int)(__float_as_uint(bA0) & 255u))
              : (511 - (int)(__float_as_uint(bB0) & 255u));
    float m1  = fmaxf(bA1, bB1);
    float m21 = fmaxf(fminf(bA1, bB1), fmaxf(b2A1, b2B1));
    int bidx1 = (bA1 >= bB1)
              ? (255 - (int)(__float_as_uint(bA1) & 255u))
              : (511 - (int)(__float_as_uint(bB1) & 255u));

    out[IDX_OFF + r0] = (float)bidx0;
    out[IDX_OFF + r1] = (float)bidx1;
    out[PH_OFF + r0] = ph0;
    out[PH_OFF + r1] = ph1;
    if (m0 - m20 < fix_thr(m0)) {
        int slot = atomicAdd(&g_fix_count, 1);
        g_fix_list[slot] = r0;
    }
    if (m1 - m21 < fix_thr(m1)) {
        int slot = atomicAdd(&g_fix_count, 1);
        g_fix_list[slot] = r1;
    }

    // Warp-cooperative coalesced gather: warp's rows are contiguous.
    int lane = tid & 31;
    int wrow0 = gid & ~31;              // first row of warp's region 0
    const float4* cb4 = (const float4*)codebook;
    float4* o4 = (float4*)out;
    #pragma unroll
    for (int i = 0; i < 16; i++) {
        int f = i * 32 + lane;          // 0..511 float4s in warp region
        int rsel = f >> 4;              // row-within-warp 0..31
        int col  = f & 15;
        int bs0 = __shfl_sync(0xFFFFFFFFu, bidx0, rsel);
        o4[(size_t)(wrow0 + rsel) * 16 + col] = cb4[bs0 * 16 + col];
    }
    int wrow1 = wrow0 + NHALF;
    #pragma unroll
    for (int i = 0; i < 16; i++) {
        int f = i * 32 + lane;
        int rsel = f >> 4;
        int col  = f & 15;
        int bs1 = __shfl_sync(0xFFFFFFFFu, bidx1, rsel);
        o4[(size_t)(wrow1 + rsel) * 16 + col] = cb4[bs1 * 16 + col];
    }
}

// ---------------------------------------------------------------------------
// Kernel 4: exact rerank for flagged rows (few now). One warp per row:
// fp32 pass from smem, fp64 only for candidates within 1e-3 of warp max.
// ---------------------------------------------------------------------------
__global__ void __launch_bounds__(256) fixup_kernel(
    const float* __restrict__ imu,
    const float* __restrict__ codebook,
    float* __restrict__ out) {

    int n = g_fix_count;
    if (blockIdx.x * 8 >= n) return;

    __shared__ float st[NCODES * PSTRIDE];   // 26 KB
    int tid = threadIdx.x;
    for (int i = tid; i < NCODES * PSTRIDE; i += 256) st[i] = g_p32s[i];
    __syncthreads();

    int lane = tid & 31;
    int warp = (blockIdx.x * blockDim.x + tid) >> 5;
    int nwarps = (gridDim.x * blockDim.x) >> 5;

    for (int i = warp; i < n; i += nwarps) {
        int row = g_fix_list[i];
        float gf[11], ph;
        load_features(imu, row, gf, ph);

        // pass 1: fp32 scores from smem (two independent chains for ILP)
        float sc[16];
        float lbest = -FLT_MAX;
        #pragma unroll
        for (int c = 0; c < 16; c += 2) {
            const float* pr0 = st + ((c)     * 32 + lane) * PSTRIDE;
            const float* pr1 = st + ((c + 1) * 32 + lane) * PSTRIDE;
            float sa = pr0[11];
            float sb = pr1[11];
            #pragma unroll
            for (int k = 0; k < 11; k++) {
                sa = fmaf(gf[k], pr0[k], sa);
                sb = fmaf(gf[k], pr1[k], sb);
            }
            sc[c] = sa;
            sc[c + 1] = sb;
            lbest = fmaxf(lbest, fmaxf(sa, sb));
        }
        #pragma unroll
        for (int m = 16; m > 0; m >>= 1)
            lbest = fmaxf(lbest, __shfl_xor_sync(0xFFFFFFFFu, lbest, m));
        float thr = lbest - 1e-3f;

        // pass 2: fp64 for candidates only
        double gd[11];
        #pragma unroll
        for (int k = 0; k < 11; k++) gd[k] = (double)gf[k];
        double bd = -1.0e300;
        int bi = NCODES;
        #pragma unroll 1
        for (int c = 0; c < 16; c++) {
            if (sc[c] >= thr) {
                int j = c * 32 + lane;
                const double* pr = g_p64 + j * PDIM;
                double s0 = pr[11];
                double s1 = 0.0;
                #pragma unroll
                for (int k = 0; k < 10; k += 2) {
                    s0 += gd[k]     * pr[k];
                    s1 += gd[k + 1] * pr[k + 1];
                }
                s0 += gd[10] * pr[10];
                double s = s0 + s1;
                if (s > bd || (s == bd && j < bi)) { bd = s; bi = j; }
            }
        }
        #pragma unroll
        for (int m = 16; m > 0; m >>= 1) {
            double od = __shfl_xor_sync(0xFFFFFFFFu, bd, m);
            int    oi = __shfl_xor_sync(0xFFFFFFFFu, bi, m);
            if (od > bd || (od == bd && oi < bi)) { bd = od; bi = oi; }
        }
        if (lane == 0) out[IDX_OFF + row] = (float)bi;
        if (lane < 16) {
            const float4* cb = (const float4*)(codebook + (size_t)bi * CODE_DIM);
            float4* oq = (float4*)(out + (size_t)row * CODE_DIM);
            oq[lane] = cb[lane];
        }
    }
}

// ---------------------------------------------------------------------------
extern "C" void kernel_launch(void* const* d_in, const int* in_sizes, int n_in,
                              void* d_out, int out_size) {
    const float* imu      = (const float*)d_in[0];
    const float* W_mag    = (const float*)d_in[1];
    const float* b_mag    = (const float*)d_in[2];
    const float* W_phase  = (const float*)d_in[3];
    const float* b_phase  = (const float*)d_in[4];
    const float* codebook = (const float*)d_in[5];
    float* out = (float*)d_out;

    phase_kernel<<<B_DIM * C_DIM, 512, 5120 * sizeof(float2)>>>(imu);
    precompute_kernel<<<NCODES, 32>>>(W_mag, b_mag, W_phase, b_phase, codebook);
    quantize_kernel<<<NHALF / 256, 256>>>(imu, codebook, out);
    fixup_kernel<<<296, 256>>>(imu, codebook, out);
}